// round 12
// baseline (speedup 1.0000x reference)
#include <cuda_runtime.h>
#include <cuda_bf16.h>
#include <math.h>
#include <stdint.h>

// Problem constants
#define TT    2048
#define DM    1024
#define NH    16
#define NKV   4
#define HD    64
#define EPSN  1e-6f
#define NQKV  1536   // fused projection width: 1024 q + 256 k + 256 v

// ---------------------------------------------------------------------------
// Device scratch (no cudaMalloc allowed)
// ---------------------------------------------------------------------------
__device__ float g_qkv[TT * NQKV];
__device__ float g_q0[TT * NH];
__device__ float g_k0[TT * NKV];
__device__ float g_qn[TT * NH];
__device__ float g_part[32];
__device__ float g_oacc1[TT * DM], g_oacc2[TT * DM];
__device__ float g_lacc1[TT * NH], g_lacc2[TT * NH];

// bf16 hi/lo split storage
__device__ uint4 g_xh[TT * DM / 8],   g_xl[TT * DM / 8];
__device__ uint4 g_wh[NQKV * DM / 8], g_wl[NQKV * DM / 8];
__device__ uint4 g_owh[DM * DM / 8],  g_owl[DM * DM / 8];
__device__ uint4 g_ah[TT * DM / 8],   g_al[TT * DM / 8];
__device__ uint4 g_qbh[TT * NH * HD / 8],  g_qbl[TT * NH * HD / 8];
__device__ uint4 g_kbh[TT * NKV * HD / 8], g_kbl[TT * NKV * HD / 8];
__device__ uint4 g_vbh[TT * NKV * HD / 8], g_vbl[TT * NKV * HD / 8];

// attention work-item schedule (heavy first): (block b, tile range [t0,t1))
__constant__ int c_ib[24]  = {15,15, 7,14,14,13,13, 6,12,12,11,11, 5,10,10, 9, 9, 4, 8, 8, 3, 2, 1, 0};
__constant__ int c_it0[24] = { 0,16, 0, 0,15, 0,14, 0, 0,13, 0,12, 0, 0,11, 0,10, 0, 0, 9, 0, 0, 0, 0};
__constant__ int c_it1[24] = {16,32,16,15,30,14,28,14,13,26,12,24,12,11,22,10,20,10, 9,18, 8, 6, 4, 2};

// ---------------------------------------------------------------------------
// PTX helpers (baseline ISA only)
// ---------------------------------------------------------------------------
__device__ __forceinline__ uint32_t smem_u32(const void* p) {
    uint32_t a;
    asm("{ .reg .u64 t; cvta.to.shared.u64 t, %1; cvt.u32.u64 %0, t; }" : "=r"(a) : "l"(p));
    return a;
}
__device__ __forceinline__ void ldsm_x4(uint32_t* r, uint32_t addr) {
    asm volatile("ldmatrix.sync.aligned.m8n8.x4.shared.b16 {%0,%1,%2,%3}, [%4];"
                 : "=r"(r[0]), "=r"(r[1]), "=r"(r[2]), "=r"(r[3]) : "r"(addr));
}
__device__ __forceinline__ void ldsm_x4_t(uint32_t* r, uint32_t addr) {
    asm volatile("ldmatrix.sync.aligned.m8n8.x4.trans.shared.b16 {%0,%1,%2,%3}, [%4];"
                 : "=r"(r[0]), "=r"(r[1]), "=r"(r[2]), "=r"(r[3]) : "r"(addr));
}
__device__ __forceinline__ void mma16816(float* c, const uint32_t* a, uint32_t b0, uint32_t b1) {
    asm volatile("mma.sync.aligned.m16n8k16.row.col.f32.bf16.bf16.f32 "
                 "{%0,%1,%2,%3}, {%4,%5,%6,%7}, {%8,%9}, {%0,%1,%2,%3};"
                 : "+f"(c[0]), "+f"(c[1]), "+f"(c[2]), "+f"(c[3])
                 : "r"(a[0]), "r"(a[1]), "r"(a[2]), "r"(a[3]), "r"(b0), "r"(b1));
}
__device__ __forceinline__ void sts128(uint32_t addr, uint4 v) {
    asm volatile("st.shared.v4.b32 [%0], {%1,%2,%3,%4};"
                 :: "r"(addr), "r"(v.x), "r"(v.y), "r"(v.z), "r"(v.w) : "memory");
}
__device__ __forceinline__ void cpasync16(uint32_t dst, const void* src) {
    asm volatile("cp.async.cg.shared.global [%0], [%1], 16;" :: "r"(dst), "l"(src));
}
__device__ __forceinline__ void cpasync_commit() {
    asm volatile("cp.async.commit_group;" ::: "memory");
}
template <int N>
__device__ __forceinline__ void cpasync_wait() {
    asm volatile("cp.async.wait_group %0;" :: "n"(N) : "memory");
}
__device__ __forceinline__ float fsqrt_ap(float x) {
    float r; asm("sqrt.approx.f32 %0, %1;" : "=f"(r) : "f"(x)); return r;
}
__device__ __forceinline__ float flg2(float x) {
    float r; asm("lg2.approx.f32 %0, %1;" : "=f"(r) : "f"(x)); return r;
}
__device__ __forceinline__ float fex2(float x) {
    float r; asm("ex2.approx.f32 %0, %1;" : "=f"(r) : "f"(x)); return r;
}
#define SW128(o) ((o) ^ (((o) >> 3) & 0x70))

__device__ __forceinline__ uint16_t bf_hi(float f, float& rem) {
    __nv_bfloat16 h = __float2bfloat16(f);
    rem = f - __bfloat162float(h);
    union { __nv_bfloat16 b; uint16_t u; } cv; cv.b = h;
    return cv.u;
}
__device__ __forceinline__ uint16_t bf_of(float f) {
    union { __nv_bfloat16 b; uint16_t u; } cv; cv.b = __float2bfloat16(f);
    return cv.u;
}

// ---------------------------------------------------------------------------
// Merged fp32 -> bf16 hi/lo conversion; 4 contiguous float4 per thread (MLP 4).
// All region sizes are multiples of 4 float4s, so one branch per thread.
// ---------------------------------------------------------------------------
#define N4_X  (TT * DM / 4)
#define N4_QW (DM * DM / 4)
#define N4_KW (256 * DM / 4)
#define N4_VW (256 * DM / 4)
#define N4_OW (DM * DM / 4)
#define N4_TOT (N4_X + N4_QW + N4_KW + N4_VW + N4_OW)

__global__ __launch_bounds__(256) void conv_all(
    const float* __restrict__ x, const float* __restrict__ qw,
    const float* __restrict__ kw, const float* __restrict__ vw,
    const float* __restrict__ ow,
    char* xh, char* xl, char* qwh, char* qwl, char* kwh, char* kwl,
    char* vwh, char* vwl, char* owh, char* owl) {
    int i = (blockIdx.x * 256 + threadIdx.x) * 4;
    if (i >= N4_TOT) return;
    const float* in; char* hi; char* lo; int base;
    if (i < N4_X)                          { in = x;  hi = xh;  lo = xl;  base = 0; }
    else if (i < N4_X + N4_QW)             { in = qw; hi = qwh; lo = qwl; base = N4_X; }
    else if (i < N4_X + N4_QW + N4_KW)     { in = kw; hi = kwh; lo = kwl; base = N4_X + N4_QW; }
    else if (i < N4_X + N4_QW + N4_KW + N4_VW)
                                           { in = vw; hi = vwh; lo = vwl; base = N4_X + N4_QW + N4_KW; }
    else                                   { in = ow; hi = owh; lo = owl; base = N4_X + N4_QW + N4_KW + N4_VW; }
    int j4 = i - base;
    float4 v[4];
#pragma unroll
    for (int k = 0; k < 4; k++) v[k] = ((const float4*)in)[j4 + k];
#pragma unroll
    for (int k = 0; k < 4; k++) {
        union { __nv_bfloat16 b[4]; uint2 u; } h, l;
        float f[4] = {v[k].x, v[k].y, v[k].z, v[k].w};
#pragma unroll
        for (int j = 0; j < 4; j++) {
            h.b[j] = __float2bfloat16(f[j]);
            l.b[j] = __float2bfloat16(f[j] - __bfloat162float(h.b[j]));
        }
        ((uint2*)hi)[j4 + k] = h.u;
        ((uint2*)lo)[j4 + k] = l.u;
    }
}

// ---------------------------------------------------------------------------
// HMMA bf16 hi/lo-split GEMM with cp.async 3-stage pipeline (unchanged).
// ---------------------------------------------------------------------------
#define TILE_B 16384
#define STAGE_B (4 * TILE_B)
#define GEMM_SMEM_BYTES (3 * STAGE_B + 1024)

__global__ __launch_bounds__(256) void gemm_mma_hl(
    const char* __restrict__ Ah, const char* __restrict__ Al,
    const char* __restrict__ Bh, const char* __restrict__ Bl,
    float* __restrict__ C, int Ntot, int K) {
    extern __shared__ __align__(16) char sm[];
    uint32_t ts = (smem_u32(sm) + 1023) & ~1023u;
    const uint32_t stage[3] = { ts, ts + STAGE_B, ts + 2 * STAGE_B };

    const int tid = threadIdx.x;
    const int lane = tid & 31;
    const int wid = tid >> 5;
    const int wm = wid >> 1;
    const int wn = wid & 1;
    const int m0 = blockIdx.y * 128;
    const int n0 = blockIdx.x * 128;
    const size_t K2 = (size_t)K * 2;

    const char* srcs[4] = { Ah + (size_t)m0 * K2, Al + (size_t)m0 * K2,
                            Bh + (size_t)n0 * K2, Bl + (size_t)n0 * K2 };

    const int u = tid & 7;
    const int r0 = tid >> 3;

    auto load_chunk = [&](int ch, uint32_t sb) {
        const size_t koff = (size_t)ch * 128 + u * 16;
#pragma unroll
        for (int t = 0; t < 4; t++) {
            const char* src = srcs[t] + koff;
            const uint32_t tb = sb + t * TILE_B;
#pragma unroll
            for (int it = 0; it < 4; it++) {
                const int row = it * 32 + r0;
                uint32_t off = row * 128 + u * 16;
                cpasync16(tb + SW128(off), src + (size_t)row * K2);
            }
        }
    };

    float acc[2][8][4];
#pragma unroll
    for (int a = 0; a < 2; a++)
#pragma unroll
        for (int b = 0; b < 8; b++)
#pragma unroll
            for (int cc = 0; cc < 4; cc++) acc[a][b][cc] = 0.f;

    const int amat = lane >> 3, arow = lane & 7;
    const int nch = K / 64;

    load_chunk(0, stage[0]);
    cpasync_commit();
    if (nch > 1) {
        load_chunk(1, stage[1]);
        cpasync_commit();
    }

    for (int ch = 0; ch < nch; ch++) {
        if (ch + 2 < nch) {
            load_chunk(ch + 2, stage[(ch + 2) % 3]);
            cpasync_commit();
            cpasync_wait<2>();
        } else if (ch + 1 < nch) {
            cpasync_wait<1>();
        } else {
            cpasync_wait<0>();
        }
        __syncthreads();

        const uint32_t sb = stage[ch % 3];
        const uint32_t tAh = sb, tAl = sb + TILE_B, tBh = sb + 2 * TILE_B, tBl = sb + 3 * TILE_B;
#pragma unroll
        for (int ks = 0; ks < 4; ks++) {
            uint32_t ah[2][4], al[2][4], bh[4][4], bl[4][4];
#pragma unroll
            for (int mb = 0; mb < 2; mb++) {
                int m = wm * 32 + mb * 16 + (amat & 1) * 8 + arow;
                int kb = ks * 32 + (amat >> 1) * 16;
                uint32_t off = SW128((uint32_t)(m * 128 + kb));
                ldsm_x4(ah[mb], tAh + off);
                ldsm_x4(al[mb], tAl + off);
            }
#pragma unroll
            for (int p = 0; p < 4; p++) {
                int n = wn * 64 + p * 16 + (amat >> 1) * 8 + arow;
                int kb = ks * 32 + (amat & 1) * 16;
                uint32_t off = SW128((uint32_t)(n * 128 + kb));
                ldsm_x4(bh[p], tBh + off);
                ldsm_x4(bl[p], tBl + off);
            }
#pragma unroll
            for (int mb = 0; mb < 2; mb++)
#pragma unroll
                for (int p = 0; p < 4; p++) {
                    mma16816(acc[mb][2 * p],     ah[mb], bh[p][0], bh[p][1]);
                    mma16816(acc[mb][2 * p + 1], ah[mb], bh[p][2], bh[p][3]);
                    mma16816(acc[mb][2 * p],     ah[mb], bl[p][0], bl[p][1]);
                    mma16816(acc[mb][2 * p + 1], ah[mb], bl[p][2], bl[p][3]);
                    mma16816(acc[mb][2 * p],     al[mb], bh[p][0], bh[p][1]);
                    mma16816(acc[mb][2 * p + 1], al[mb], bh[p][2], bh[p][3]);
                }
        }
        __syncthreads();
    }

    const int crow = lane >> 2;
    const int ccol = (lane & 3) * 2;
#pragma unroll
    for (int mb = 0; mb < 2; mb++) {
#pragma unroll
        for (int nb = 0; nb < 8; nb++) {
            int m = m0 + wm * 32 + mb * 16 + crow;
            int n = n0 + wn * 64 + nb * 8 + ccol;
            *(float2*)&C[(size_t)m * Ntot + n]       = make_float2(acc[mb][nb][0], acc[mb][nb][1]);
            *(float2*)&C[(size_t)(m + 8) * Ntot + n] = make_float2(acc[mb][nb][2], acc[mb][nb][3]);
        }
    }
}

// ---------------------------------------------------------------------------
// RMSNorm + RoPE (+ sqrt(c) prescale); q0/k0 = sqrt(1 + c|v|^2).
// ---------------------------------------------------------------------------
__global__ __launch_bounds__(256) void rms_rope_kernel(
    const float* __restrict__ qkv,
    char* __restrict__ qbh, char* __restrict__ qbl,
    char* __restrict__ kbh, char* __restrict__ kbl,
    float* __restrict__ q0, float* __restrict__ k0,
    float* __restrict__ qn, const float* __restrict__ curv) {
    const int wid = threadIdx.x >> 5;
    const int lane = threadIdx.x & 31;
    const int vi = blockIdx.x * 8 + wid;
    const int t = vi & 2047;
    const int hh = vi >> 11;

    const float* vec;
    size_t obase;
    char *oh, *ol;
    if (hh < NH) {
        vec = qkv + (size_t)t * NQKV + hh * HD;
        obase = ((size_t)t * NH + hh) * HD; oh = qbh; ol = qbl;
    } else {
        vec = qkv + (size_t)t * NQKV + 1024 + (hh - NH) * HD;
        obase = ((size_t)t * NKV + (hh - NH)) * HD; oh = kbh; ol = kbl;
    }
    float x1 = vec[lane], x2 = vec[lane + 32];
    float ss = x1 * x1 + x2 * x2;
#pragma unroll
    for (int o = 16; o >= 1; o >>= 1) ss += __shfl_xor_sync(0xffffffffu, ss, o);

    float inv = rsqrtf(ss * (1.0f / 64.0f) + EPSN);
    x1 *= inv; x2 *= inv;

    float invf = expf(-(float)lane * 0.28782313662425572f);
    float ang = (float)t * invf;
    float sv, cv;
    sincosf(ang, &sv, &cv);
    float c = *curv;
    float sqc = sqrtf(c);
    float o1 = fmaf(x1, cv, x2 * sv) * sqc;
    float o2 = fmaf(-x1, sv, x2 * cv) * sqc;

    float r1, r2;
    uint16_t h1 = bf_hi(o1, r1), h2 = bf_hi(o2, r2);
    ((uint16_t*)oh)[obase + lane]      = h1;
    ((uint16_t*)oh)[obase + lane + 32] = h2;
    ((uint16_t*)ol)[obase + lane]      = bf_of(r1);
    ((uint16_t*)ol)[obase + lane + 32] = bf_of(r2);

    if (lane == 0) {
        float sum2 = ss * inv * inv;
        float h0 = sqrtf(1.0f + c * sum2);
        if (hh < NH) {
            q0[t * NH + hh] = h0;
            qn[t * NH + hh] = sqrtf(sum2);
        } else {
            k0[t * NKV + (hh - NH)] = h0;
        }
    }
}

// ---------------------------------------------------------------------------
// V slice conversion from fused buffer
// ---------------------------------------------------------------------------
__global__ __launch_bounds__(256) void v_conv(const float* __restrict__ qkv,
                                              char* __restrict__ vbh,
                                              char* __restrict__ vbl) {
    int i = blockIdx.x * 256 + threadIdx.x;
    if (i >= TT * 64) return;
    int t = i >> 6, j = i & 63;
    float4 v = *(const float4*)&qkv[(size_t)t * NQKV + 1280 + j * 4];
    union { __nv_bfloat16 b[4]; uint2 u; } h, l;
    float f[4] = {v.x, v.y, v.z, v.w};
#pragma unroll
    for (int jj = 0; jj < 4; jj++) {
        h.b[jj] = __float2bfloat16(f[jj]);
        l.b[jj] = __float2bfloat16(f[jj] - __bfloat162float(h.b[jj]));
    }
    ((uint2*)vbh)[t * 64 + j] = h.u;
    ((uint2*)vbl)[t * 64 + j] = l.u;
}

// ---------------------------------------------------------------------------
// Tensor-core flash hyperbolic attention.
// CTA = 128 q-rows x 1 head, 8 warps (2 CTAs/SM). Split-K via 24-item table.
// Fused per-key-group pipeline: S(p) -> transform(p) -> PV(p); low registers.
// ---------------------------------------------------------------------------
#define FA_STAGE_B 32768
#define FA_SMEM_BYTES (2 * FA_STAGE_B + 2560)

__global__ void __launch_bounds__(256, 2) flash_attn_mma(
    const char* __restrict__ Qh, const char* __restrict__ Ql,
    const char* __restrict__ Kh, const char* __restrict__ Kl,
    const char* __restrict__ Vh, const char* __restrict__ Vl,
    const float* __restrict__ q0a, const float* __restrict__ k0a,
    const float* __restrict__ temp, const float* __restrict__ curv,
    float* __restrict__ oacc1, float* __restrict__ oacc2,
    float* __restrict__ lacc1, float* __restrict__ lacc2) {
    extern __shared__ __align__(16) char smraw[];
    const uint32_t sb0 = (smem_u32(smraw) + 1023) & ~1023u;
    const uint32_t stg[2] = { sb0, sb0 + FA_STAGE_B };
    float* q0s = (float*)(smraw + (sb0 - smem_u32(smraw)) + 2 * FA_STAGE_B);
    float* k0st0 = q0s + 128;
    float* k0st1 = k0st0 + 64;

    const int tid = threadIdx.x;
    const int lane = tid & 31;
    const int wp = tid >> 5;                  // 0..7
    const int h = blockIdx.x;
    const int cidx = blockIdx.y;

    const int b   = c_ib[cidx];
    const int tl0 = c_it0[cidx];
    const int tl1 = c_it1[cidx];
    const int t0 = b * 128;
    const int kvh = h >> 2;

    float* ob = (tl0 == 0) ? oacc1 : oacc2;
    float* lb = (tl0 == 0) ? lacc1 : lacc2;

    const float sscale = rsqrtf(*curv) / temp[h];
    const float loclamp = 1.0f + 1e-5f;

    // ---- stage Q tile (128 rows, hi/lo) into stage0 ----
    {
        const char* qs[2] = { Qh, Ql };
        for (int idx = tid; idx < 2048; idx += 256) {
            int mtx = idx >> 10, rem = idx & 1023, row = rem >> 3, u = rem & 7;
            const char* src = qs[mtx] + ((size_t)(t0 + row) * NH + h) * 128 + u * 16;
            sts128(stg[0] + mtx * 16384 + SW128((uint32_t)(row * 128 + u * 16)), *(const uint4*)src);
        }
        if (tid < 128) q0s[tid] = q0a[(t0 + tid) * NH + h];
    }
    __syncthreads();

    // ---- Q fragments to registers (warp wp: rows 16wp..16wp+15) ----
    uint32_t qa_h[4][4], qa_l[4][4];
    const int g = lane >> 3, lr = lane & 7;
    {
        const int row = 16 * wp + (g & 1) * 8 + lr;
#pragma unroll
        for (int ks = 0; ks < 4; ks++) {
            uint32_t off = SW128((uint32_t)(row * 128 + ks * 32 + (g >> 1) * 16));
            ldsm_x4(qa_h[ks], stg[0] + off);
            ldsm_x4(qa_l[ks], stg[0] + 16384 + off);
        }
    }
    const int r = lane >> 2;
    const int colb = (lane & 3) * 2;
    const float q0r0 = q0s[16 * wp + r];
    const float q0r1 = q0s[16 * wp + 8 + r];
    const int rl0 = t0 + 16 * wp + r;
    const int rl1 = rl0 + 8;
    __syncthreads();

    float o[8][4];
#pragma unroll
    for (int i = 0; i < 8; i++)
#pragma unroll
        for (int j = 0; j < 4; j++) o[i][j] = 0.f;
    float lsum0 = 0.f, lsum1 = 0.f;

    const char* kvsrc[4] = { Kh + kvh * 128, Kl + kvh * 128, Vh + kvh * 128, Vl + kvh * 128 };

    auto kv_load = [&](int c0, uint32_t sbase, float* k0dst) {
        for (int idx = tid; idx < 2048; idx += 256) {
            int mtx = idx >> 9, rem = idx & 511, row = rem >> 3, u = rem & 7;
            const char* src = kvsrc[mtx] + (size_t)(c0 + row) * 512 + u * 16;
            cpasync16(sbase + mtx * 8192 + SW128((uint32_t)(row * 128 + u * 16)), src);
        }
        if (tid < 64) k0dst[tid] = k0a[(c0 + tid) * NKV + kvh];
    };

    kv_load(tl0 * 64, stg[tl0 & 1], (tl0 & 1) ? k0st1 : k0st0);
    cpasync_commit();

    for (int ch = tl0; ch < tl1; ch++) {
        if (ch + 1 < tl1) {
            kv_load((ch + 1) * 64, stg[(ch + 1) & 1], ((ch + 1) & 1) ? k0st1 : k0st0);
            cpasync_commit();
            cpasync_wait<1>();
        } else {
            cpasync_wait<0>();
        }
        __syncthreads();

        const uint32_t sKh = stg[ch & 1], sKl = sKh + 8192, sVh = sKh + 16384, sVl = sKh + 24576;
        const float* k0s = (ch & 1) ? k0st1 : k0st0;
        const int cbase = ch * 64;

        // ---- fused per-key-group pipeline: S(p) -> transform(p) -> PV(p) ----
#pragma unroll
        for (int p = 0; p < 4; p++) {
            // S for key group p (keys cbase+16p .. +15), 3-term
            float sc0[4] = {0.f, 0.f, 0.f, 0.f};
            float sc1[4] = {0.f, 0.f, 0.f, 0.f};
            const int rowk = p * 16 + (g & 1) * 8 + lr;
#pragma unroll
            for (int ks = 0; ks < 4; ks++) {
                uint32_t off = SW128((uint32_t)(rowk * 128 + ks * 32 + (g >> 1) * 16));
                uint32_t bh[4], bl[4];
                ldsm_x4(bh, sKh + off);
                ldsm_x4(bl, sKl + off);
                mma16816(sc0, qa_h[ks], bh[0], bh[2]);
                mma16816(sc1, qa_h[ks], bh[1], bh[3]);
                mma16816(sc0, qa_h[ks], bl[0], bl[2]);
                mma16816(sc1, qa_h[ks], bl[1], bl[3]);
                mma16816(sc0, qa_l[ks], bh[0], bh[2]);
                mma16816(sc1, qa_l[ks], bh[1], bh[3]);
            }

            // transform 8 scores -> P fragment (hi/lo)
            uint32_t phl[4], pll[4];
            {
                float k00 = k0s[p * 16 + colb];
                float k01 = k0s[p * 16 + colb + 1];
                float k08 = k0s[p * 16 + 8 + colb];
                float k09 = k0s[p * 16 + 8 + colb + 1];
                const int c0i = cbase + p * 16 + colb;

                float w0, w1, w2, w3, w4, w5, w6, w7;
                { float arg = fmaxf(fmaf(q0r0, k00, -sc0[0]), loclamp);
                  float z = arg + fsqrt_ap(fmaf(arg, arg, -1.f));
                  w0 = fex2(-sscale * flg2(z)); }
                { float arg = fmaxf(fmaf(q0r0, k01, -sc0[1]), loclamp);
                  float z = arg + fsqrt_ap(fmaf(arg, arg, -1.f));
                  w1 = fex2(-sscale * flg2(z)); }
                { float arg = fmaxf(fmaf(q0r1, k00, -sc0[2]), loclamp);
                  float z = arg + fsqrt_ap(fmaf(arg, arg, -1.f));
                  w2 = fex2(-sscale * flg2(z)); }
                { float arg = fmaxf(fmaf(q0r1, k01, -sc0[3]), loclamp);
                  float z = arg + fsqrt_ap(fmaf(arg, arg, -1.f));
                  w3 = fex2(-sscale * flg2(z)); }
                { float arg = fmaxf(fmaf(q0r0, k08, -sc1[0]), loclamp);
                  float z = arg + fsqrt_ap(fmaf(arg, arg, -1.f));
                  w4 = fex2(-sscale * flg2(z)); }
                { float arg = fmaxf(fmaf(q0r0, k09, -sc1[1]), loclamp);
                  float z = arg + fsqrt_ap(fmaf(arg, arg, -1.f));
                  w5 = fex2(-sscale * flg2(z)); }
                { float arg = fmaxf(fmaf(q0r1, k08, -sc1[2]), loclamp);
                  float z = arg + fsqrt_ap(fmaf(arg, arg, -1.f));
                  w6 = fex2(-sscale * flg2(z)); }
                { float arg = fmaxf(fmaf(q0r1, k09, -sc1[3]), loclamp);
                  float z = arg + fsqrt_ap(fmaf(arg, arg, -1.f));
                  w7 = fex2(-sscale * flg2(z)); }

                if (c0i > rl0)     w0 = 0.f;
                if (c0i + 1 > rl0) w1 = 0.f;
                if (c0i > rl1)     w2 = 0.f;
                if (c0i + 1 > rl1) w3 = 0.f;
                if (c0i + 8 > rl0) w4 = 0.f;
                if (c0i + 9 > rl0) w5 = 0.f;
                if (c0i + 8 > rl1) w6 = 0.f;
                if (c0i + 9 > rl1) w7 = 0.f;

                lsum0 += (w0 + w1) + (w4 + w5);
                lsum1 += (w2 + w3) + (w6 + w7);

                float r0f, r1f, r2f, r3f, r4f, r5f, r6f, r7f;
                phl[0] = (uint32_t)bf_hi(w0, r0f) | ((uint32_t)bf_hi(w1, r1f) << 16);
                phl[1] = (uint32_t)bf_hi(w2, r2f) | ((uint32_t)bf_hi(w3, r3f) << 16);
                phl[2] = (uint32_t)bf_hi(w4, r4f) | ((uint32_t)bf_hi(w5, r5f) << 16);
                phl[3] = (uint32_t)bf_hi(w6, r6f) | ((uint32_t)bf_hi(w7, r7f) << 16);
                pll[0] = (uint32_t)bf_of(r0f) | ((uint32_t)bf_of(r1f) << 16);
                pll[1] = (uint32_t)bf_of(r2f) | ((uint32_t)bf_of(r3f) << 16);
                pll[2] = (uint32_t)bf_of(r4f) | ((uint32_t)bf_of(r5f) << 16);
                pll[3] = (uint32_t)bf_of(r6f) | ((uint32_t)bf_of(r7f) << 16);
            }

            // PV ks-step p (keys cbase+16p..+15), 3-term
            const int rowv = p * 16 + (g & 1) * 8 + lr;
#pragma unroll
            for (int dp = 0; dp < 4; dp++) {
                uint32_t off = SW128((uint32_t)(rowv * 128 + dp * 32 + (g >> 1) * 16));
                uint32_t bvh[4], bvl[4];
                ldsm_x4_t(bvh, sVh + off);
                ldsm_x4_t(bvl, sVl + off);
                mma16816(o[2 * dp],     phl, bvh[0], bvh[1]);
                mma16816(o[2 * dp + 1], phl, bvh[2], bvh[3]);
                mma16816(o[2 * dp],     phl, bvl[0], bvl[1]);
                mma16816(o[2 * dp + 1], phl, bvl[2], bvl[3]);
                mma16816(o[2 * dp],     pll, bvh[0], bvh[1]);
                mma16816(o[2 * dp + 1], pll, bvh[2], bvh[3]);
            }
        }
        __syncthreads();
    }

    // ---- epilogue: store unnormalized partials ----
    lsum0 += __shfl_xor_sync(0xffffffffu, lsum0, 1);
    lsum0 += __shfl_xor_sync(0xffffffffu, lsum0, 2);
    lsum1 += __shfl_xor_sync(0xffffffffu, lsum1, 1);
    lsum1 += __shfl_xor_sync(0xffffffffu, lsum1, 2);

#pragma unroll
    for (int nb = 0; nb < 8; nb++) {
        int col = h * 64 + nb * 8 + colb;
        *(float2*)&ob[(size_t)rl0 * DM + col] = make_float2(o[nb][0], o[nb][1]);
        *(float2*)&ob[(size_t)rl1 * DM + col] = make_float2(o[nb][2], o[nb][3]);
    }
    if ((lane & 3) == 0) {
        lb[rl0 * NH + h] = lsum0;
        lb[rl1 * NH + h] = lsum1;
    }
}

// ---------------------------------------------------------------------------
// merge split partials, normalize, emit bf16 hi/lo attn output.
// ---------------------------------------------------------------------------
__global__ __launch_bounds__(256) void merge_norm(
    const float* __restrict__ oacc1, const float* __restrict__ oacc2,
    const float* __restrict__ lacc1, const float* __restrict__ lacc2,
    char* __restrict__ ah, char* __restrict__ al) {
    int j = threadIdx.x;
    int rowid = blockIdx.x * 16 + (j >> 4);
    int t = rowid >> 4;
    int hh = rowid & 15;
    int dd = (j & 15) * 4;
    bool two = (t >= 1024);

    float l = lacc1[rowid] + (two ? lacc2[rowid] : 0.f);
    size_t base = (size_t)t * DM + hh * 64 + dd;
    float4 ov = *(const float4*)&oacc1[base];
    if (two) {
        float4 o2 = *(const float4*)&oacc2[base];
        ov.x += o2.x; ov.y += o2.y; ov.z += o2.z; ov.w += o2.w;
    }
    float invl = 1.0f / l;
    float f[4] = {ov.x * invl, ov.y * invl, ov.z * invl, ov.w * invl};
    union { uint16_t u[4]; uint2 v; } hb, lb2;
#pragma unroll
    for (int k = 0; k < 4; k++) {
        float rem;
        hb.u[k] = bf_hi(f[k], rem);
        lb2.u[k] = bf_of(rem);
    }
    *(uint2*)(ah + base * 2) = hb.v;
    *(uint2*)(al + base * 2) = lb2.v;
}

// ---------------------------------------------------------------------------
// spatial_norm: two-stage reduction
// ---------------------------------------------------------------------------
__global__ __launch_bounds__(256) void norm_partial(const float* __restrict__ qn,
                                                    float* __restrict__ part) {
    __shared__ float red[256];
    int tid = threadIdx.x;
    float s = 0.f;
    for (int i = blockIdx.x * 256 + tid; i < TT * NH; i += 32 * 256) s += qn[i];
    red[tid] = s;
    __syncthreads();
#pragma unroll
    for (int k = 128; k > 0; k >>= 1) {
        if (tid < k) red[tid] += red[tid + k];
        __syncthreads();
    }
    if (tid == 0) part[blockIdx.x] = red[0];
}
__global__ __launch_bounds__(32) void norm_final(const float* __restrict__ part,
                                                 float* __restrict__ out_scalar) {
    int tid = threadIdx.x;
    float s = part[tid];
#pragma unroll
    for (int o = 16; o >= 1; o >>= 1) s += __shfl_xor_sync(0xffffffffu, s, o);
    if (tid == 0) *out_scalar = s * (1.0f / (float)(TT * NH));
}

// ---------------------------------------------------------------------------
// Launch
// ---------------------------------------------------------------------------
extern "C" void kernel_launch(void* const* d_in, const int* in_sizes, int n_in,
                              void* d_out, int out_size) {
    const float* x    = (const float*)d_in[0];
    const float* q_w  = (const float*)d_in[1];
    const float* k_w  = (const float*)d_in[2];
    const float* v_w  = (const float*)d_in[3];
    const float* o_w  = (const float*)d_in[4];
    const float* temp = (const float*)d_in[5];
    const float* curv = (const float*)d_in[6];
    float* out = (float*)d_out;

    float *pqkv, *pq0, *pk0, *pqn, *ppart, *po1, *po2, *pl1, *pl2;
    char *xh, *xl, *wh, *wl, *owh, *owl, *ah, *al;
    char *qbh, *qbl, *kbh, *kbl, *vbh, *vbl;
    cudaGetSymbolAddress((void**)&pqkv, g_qkv);
    cudaGetSymbolAddress((void**)&pq0, g_q0);
    cudaGetSymbolAddress((void**)&pk0, g_k0);
    cudaGetSymbolAddress((void**)&pqn, g_qn);
    cudaGetSymbolAddress((void**)&ppart, g_part);
    cudaGetSymbolAddress((void**)&po1, g_oacc1);
    cudaGetSymbolAddress((void**)&po2, g_oacc2);
    cudaGetSymbolAddress((void**)&pl1, g_lacc1);
    cudaGetSymbolAddress((void**)&pl2, g_lacc2);
    cudaGetSymbolAddress((void**)&xh, g_xh);
    cudaGetSymbolAddress((void**)&xl, g_xl);
    cudaGetSymbolAddress((void**)&wh, g_wh);
    cudaGetSymbolAddress((void**)&wl, g_wl);
    cudaGetSymbolAddress((void**)&owh, g_owh);
    cudaGetSymbolAddress((void**)&owl, g_owl);
    cudaGetSymbolAddress((void**)&ah, g_ah);
    cudaGetSymbolAddress((void**)&al, g_al);
    cudaGetSymbolAddress((void**)&qbh, g_qbh);
    cudaGetSymbolAddress((void**)&qbl, g_qbl);
    cudaGetSymbolAddress((void**)&kbh, g_kbh);
    cudaGetSymbolAddress((void**)&kbl, g_kbl);
    cudaGetSymbolAddress((void**)&vbh, g_vbh);
    cudaGetSymbolAddress((void**)&vbl, g_vbl);

    cudaFuncSetAttribute(gemm_mma_hl, cudaFuncAttributeMaxDynamicSharedMemorySize,
                         GEMM_SMEM_BYTES);
    cudaFuncSetAttribute(flash_attn_mma, cudaFuncAttributeMaxDynamicSharedMemorySize,
                         FA_SMEM_BYTES);

    char* qwh = wh;                         char* qwl = wl;
    char* kwh = wh + (size_t)1024 * DM * 2; char* kwl = wl + (size_t)1024 * DM * 2;
    char* vwh = wh + (size_t)1280 * DM * 2; char* vwl = wl + (size_t)1280 * DM * 2;

    conv_all<<<(N4_TOT / 4 + 255) / 256, 256>>>(x, q_w, k_w, v_w, o_w,
                                                xh, xl, qwh, qwl, kwh, kwl,
                                                vwh, vwl, owh, owl);

    gemm_mma_hl<<<dim3(NQKV / 128, TT / 128), 256, GEMM_SMEM_BYTES>>>(
        xh, xl, wh, wl, pqkv, NQKV, DM);

    rms_rope_kernel<<<TT * (NH + NKV) / 8, 256>>>(pqkv, qbh, qbl, kbh, kbl,
                                                  pq0, pk0, pqn, curv);
    v_conv<<<(TT * 64 + 255) / 256, 256>>>(pqkv, vbh, vbl);

    flash_attn_mma<<<dim3(NH, 24), 256, FA_SMEM_BYTES>>>(
        qbh, qbl, kbh, kbl, vbh, vbl, pq0, pk0, temp, curv,
        po1, po2, pl1, pl2);

    merge_norm<<<TT * NH / 16, 256>>>(po1, po2, pl1, pl2, ah, al);

    gemm_mma_hl<<<dim3(DM / 128, TT / 128), 256, GEMM_SMEM_BYTES>>>(
        ah, al, owh, owl, out, DM, DM);

    norm_partial<<<32, 256>>>(pqn, ppart);
    norm_final<<<1, 32>>>(ppart, out + (out_size - 1));
}

// round 13
// speedup vs baseline: 1.0739x; 1.0739x over previous
#include <cuda_runtime.h>
#include <cuda_bf16.h>
#include <cuda_fp16.h>
#include <math.h>
#include <stdint.h>

// Problem constants
#define TT    2048
#define DM    1024
#define NH    16
#define NKV   4
#define HD    64
#define EPSN  1e-6f
#define NQKV  1536   // fused projection width: 1024 q + 256 k + 256 v

// ---------------------------------------------------------------------------
// Device scratch (no cudaMalloc allowed)
// ---------------------------------------------------------------------------
__device__ float g_qkv[TT * NQKV];
__device__ float g_q0[TT * NH];
__device__ float g_k0[TT * NKV];
__device__ float g_qn[TT * NH];
__device__ float g_part[32];
__device__ float g_oacc1[TT * DM], g_oacc2[TT * DM];
__device__ float g_lacc1[TT * NH], g_lacc2[TT * NH];

// bf16 hi/lo split storage (x, weights, attn output)
__device__ uint4 g_xh[TT * DM / 8],   g_xl[TT * DM / 8];
__device__ uint4 g_wh[NQKV * DM / 8], g_wl[NQKV * DM / 8];
__device__ uint4 g_owh[DM * DM / 8],  g_owl[DM * DM / 8];
__device__ uint4 g_ah[TT * DM / 8],   g_al[TT * DM / 8];
__device__ uint4 g_qbh[TT * NH * HD / 8],  g_qbl[TT * NH * HD / 8];
__device__ uint4 g_kbh[TT * NKV * HD / 8], g_kbl[TT * NKV * HD / 8];
// V stored as fp16 hi/lo (PV path runs fp16 mma)
__device__ uint4 g_vbh[TT * NKV * HD / 8], g_vbl[TT * NKV * HD / 8];

// attention work-item schedule (heavy first): (block b, tile range [t0,t1))
__constant__ int c_ib[24]  = {15,15, 7,14,14,13,13, 6,12,12,11,11, 5,10,10, 9, 9, 4, 8, 8, 3, 2, 1, 0};
__constant__ int c_it0[24] = { 0,16, 0, 0,15, 0,14, 0, 0,13, 0,12, 0, 0,11, 0,10, 0, 0, 9, 0, 0, 0, 0};
__constant__ int c_it1[24] = {16,32,16,15,30,14,28,14,13,26,12,24,12,11,22,10,20,10, 9,18, 8, 6, 4, 2};

// ---------------------------------------------------------------------------
// PTX helpers (baseline ISA only)
// ---------------------------------------------------------------------------
__device__ __forceinline__ uint32_t smem_u32(const void* p) {
    uint32_t a;
    asm("{ .reg .u64 t; cvta.to.shared.u64 t, %1; cvt.u32.u64 %0, t; }" : "=r"(a) : "l"(p));
    return a;
}
__device__ __forceinline__ void ldsm_x4(uint32_t* r, uint32_t addr) {
    asm volatile("ldmatrix.sync.aligned.m8n8.x4.shared.b16 {%0,%1,%2,%3}, [%4];"
                 : "=r"(r[0]), "=r"(r[1]), "=r"(r[2]), "=r"(r[3]) : "r"(addr));
}
__device__ __forceinline__ void ldsm_x4_t(uint32_t* r, uint32_t addr) {
    asm volatile("ldmatrix.sync.aligned.m8n8.x4.trans.shared.b16 {%0,%1,%2,%3}, [%4];"
                 : "=r"(r[0]), "=r"(r[1]), "=r"(r[2]), "=r"(r[3]) : "r"(addr));
}
__device__ __forceinline__ void mma16816(float* c, const uint32_t* a, uint32_t b0, uint32_t b1) {
    asm volatile("mma.sync.aligned.m16n8k16.row.col.f32.bf16.bf16.f32 "
                 "{%0,%1,%2,%3}, {%4,%5,%6,%7}, {%8,%9}, {%0,%1,%2,%3};"
                 : "+f"(c[0]), "+f"(c[1]), "+f"(c[2]), "+f"(c[3])
                 : "r"(a[0]), "r"(a[1]), "r"(a[2]), "r"(a[3]), "r"(b0), "r"(b1));
}
__device__ __forceinline__ void mma16816f16(float* c, const uint32_t* a, uint32_t b0, uint32_t b1) {
    asm volatile("mma.sync.aligned.m16n8k16.row.col.f32.f16.f16.f32 "
                 "{%0,%1,%2,%3}, {%4,%5,%6,%7}, {%8,%9}, {%0,%1,%2,%3};"
                 : "+f"(c[0]), "+f"(c[1]), "+f"(c[2]), "+f"(c[3])
                 : "r"(a[0]), "r"(a[1]), "r"(a[2]), "r"(a[3]), "r"(b0), "r"(b1));
}
__device__ __forceinline__ void sts128(uint32_t addr, uint4 v) {
    asm volatile("st.shared.v4.b32 [%0], {%1,%2,%3,%4};"
                 :: "r"(addr), "r"(v.x), "r"(v.y), "r"(v.z), "r"(v.w) : "memory");
}
__device__ __forceinline__ void cpasync16(uint32_t dst, const void* src) {
    asm volatile("cp.async.cg.shared.global [%0], [%1], 16;" :: "r"(dst), "l"(src));
}
__device__ __forceinline__ void cpasync_commit() {
    asm volatile("cp.async.commit_group;" ::: "memory");
}
template <int N>
__device__ __forceinline__ void cpasync_wait() {
    asm volatile("cp.async.wait_group %0;" :: "n"(N) : "memory");
}
__device__ __forceinline__ float fsqrt_ap(float x) {
    float r; asm("sqrt.approx.f32 %0, %1;" : "=f"(r) : "f"(x)); return r;
}
__device__ __forceinline__ float flg2(float x) {
    float r; asm("lg2.approx.f32 %0, %1;" : "=f"(r) : "f"(x)); return r;
}
__device__ __forceinline__ float fex2(float x) {
    float r; asm("ex2.approx.f32 %0, %1;" : "=f"(r) : "f"(x)); return r;
}
#define SW128(o) ((o) ^ (((o) >> 3) & 0x70))

__device__ __forceinline__ uint16_t bf_hi(float f, float& rem) {
    __nv_bfloat16 h = __float2bfloat16(f);
    rem = f - __bfloat162float(h);
    union { __nv_bfloat16 b; uint16_t u; } cv; cv.b = h;
    return cv.u;
}
__device__ __forceinline__ uint16_t bf_of(float f) {
    union { __nv_bfloat16 b; uint16_t u; } cv; cv.b = __float2bfloat16(f);
    return cv.u;
}
__device__ __forceinline__ uint16_t f16_hi(float f, float& rem) {
    __half h = __float2half_rn(f);
    rem = f - __half2float(h);
    union { __half b; uint16_t u; } cv; cv.b = h;
    return cv.u;
}
__device__ __forceinline__ uint16_t f16_of(float f) {
    union { __half b; uint16_t u; } cv; cv.b = __float2half_rn(f);
    return cv.u;
}

// ---------------------------------------------------------------------------
// Merged fp32 -> bf16 hi/lo conversion; 4 contiguous float4 per thread (MLP 4).
// ---------------------------------------------------------------------------
#define N4_X  (TT * DM / 4)
#define N4_QW (DM * DM / 4)
#define N4_KW (256 * DM / 4)
#define N4_VW (256 * DM / 4)
#define N4_OW (DM * DM / 4)
#define N4_TOT (N4_X + N4_QW + N4_KW + N4_VW + N4_OW)

__global__ __launch_bounds__(256) void conv_all(
    const float* __restrict__ x, const float* __restrict__ qw,
    const float* __restrict__ kw, const float* __restrict__ vw,
    const float* __restrict__ ow,
    char* xh, char* xl, char* qwh, char* qwl, char* kwh, char* kwl,
    char* vwh, char* vwl, char* owh, char* owl) {
    int i = (blockIdx.x * 256 + threadIdx.x) * 4;
    if (i >= N4_TOT) return;
    const float* in; char* hi; char* lo; int base;
    if (i < N4_X)                          { in = x;  hi = xh;  lo = xl;  base = 0; }
    else if (i < N4_X + N4_QW)             { in = qw; hi = qwh; lo = qwl; base = N4_X; }
    else if (i < N4_X + N4_QW + N4_KW)     { in = kw; hi = kwh; lo = kwl; base = N4_X + N4_QW; }
    else if (i < N4_X + N4_QW + N4_KW + N4_VW)
                                           { in = vw; hi = vwh; lo = vwl; base = N4_X + N4_QW + N4_KW; }
    else                                   { in = ow; hi = owh; lo = owl; base = N4_X + N4_QW + N4_KW + N4_VW; }
    int j4 = i - base;
    float4 v[4];
#pragma unroll
    for (int k = 0; k < 4; k++) v[k] = ((const float4*)in)[j4 + k];
#pragma unroll
    for (int k = 0; k < 4; k++) {
        union { __nv_bfloat16 b[4]; uint2 u; } h, l;
        float f[4] = {v[k].x, v[k].y, v[k].z, v[k].w};
#pragma unroll
        for (int j = 0; j < 4; j++) {
            h.b[j] = __float2bfloat16(f[j]);
            l.b[j] = __float2bfloat16(f[j] - __bfloat162float(h.b[j]));
        }
        ((uint2*)hi)[j4 + k] = h.u;
        ((uint2*)lo)[j4 + k] = l.u;
    }
}

// ---------------------------------------------------------------------------
// HMMA bf16 hi/lo-split GEMM with cp.async 3-stage pipeline (unchanged).
// ---------------------------------------------------------------------------
#define TILE_B 16384
#define STAGE_B (4 * TILE_B)
#define GEMM_SMEM_BYTES (3 * STAGE_B + 1024)

__global__ __launch_bounds__(256) void gemm_mma_hl(
    const char* __restrict__ Ah, const char* __restrict__ Al,
    const char* __restrict__ Bh, const char* __restrict__ Bl,
    float* __restrict__ C, int Ntot, int K) {
    extern __shared__ __align__(16) char sm[];
    uint32_t ts = (smem_u32(sm) + 1023) & ~1023u;
    const uint32_t stage[3] = { ts, ts + STAGE_B, ts + 2 * STAGE_B };

    const int tid = threadIdx.x;
    const int lane = tid & 31;
    const int wid = tid >> 5;
    const int wm = wid >> 1;
    const int wn = wid & 1;
    const int m0 = blockIdx.y * 128;
    const int n0 = blockIdx.x * 128;
    const size_t K2 = (size_t)K * 2;

    const char* srcs[4] = { Ah + (size_t)m0 * K2, Al + (size_t)m0 * K2,
                            Bh + (size_t)n0 * K2, Bl + (size_t)n0 * K2 };

    const int u = tid & 7;
    const int r0 = tid >> 3;

    auto load_chunk = [&](int ch, uint32_t sb) {
        const size_t koff = (size_t)ch * 128 + u * 16;
#pragma unroll
        for (int t = 0; t < 4; t++) {
            const char* src = srcs[t] + koff;
            const uint32_t tb = sb + t * TILE_B;
#pragma unroll
            for (int it = 0; it < 4; it++) {
                const int row = it * 32 + r0;
                uint32_t off = row * 128 + u * 16;
                cpasync16(tb + SW128(off), src + (size_t)row * K2);
            }
        }
    };

    float acc[2][8][4];
#pragma unroll
    for (int a = 0; a < 2; a++)
#pragma unroll
        for (int b = 0; b < 8; b++)
#pragma unroll
            for (int cc = 0; cc < 4; cc++) acc[a][b][cc] = 0.f;

    const int amat = lane >> 3, arow = lane & 7;
    const int nch = K / 64;

    load_chunk(0, stage[0]);
    cpasync_commit();
    if (nch > 1) {
        load_chunk(1, stage[1]);
        cpasync_commit();
    }

    for (int ch = 0; ch < nch; ch++) {
        if (ch + 2 < nch) {
            load_chunk(ch + 2, stage[(ch + 2) % 3]);
            cpasync_commit();
            cpasync_wait<2>();
        } else if (ch + 1 < nch) {
            cpasync_wait<1>();
        } else {
            cpasync_wait<0>();
        }
        __syncthreads();

        const uint32_t sb = stage[ch % 3];
        const uint32_t tAh = sb, tAl = sb + TILE_B, tBh = sb + 2 * TILE_B, tBl = sb + 3 * TILE_B;
#pragma unroll
        for (int ks = 0; ks < 4; ks++) {
            uint32_t ah[2][4], al[2][4], bh[4][4], bl[4][4];
#pragma unroll
            for (int mb = 0; mb < 2; mb++) {
                int m = wm * 32 + mb * 16 + (amat & 1) * 8 + arow;
                int kb = ks * 32 + (amat >> 1) * 16;
                uint32_t off = SW128((uint32_t)(m * 128 + kb));
                ldsm_x4(ah[mb], tAh + off);
                ldsm_x4(al[mb], tAl + off);
            }
#pragma unroll
            for (int p = 0; p < 4; p++) {
                int n = wn * 64 + p * 16 + (amat >> 1) * 8 + arow;
                int kb = ks * 32 + (amat & 1) * 16;
                uint32_t off = SW128((uint32_t)(n * 128 + kb));
                ldsm_x4(bh[p], tBh + off);
                ldsm_x4(bl[p], tBl + off);
            }
#pragma unroll
            for (int mb = 0; mb < 2; mb++)
#pragma unroll
                for (int p = 0; p < 4; p++) {
                    mma16816(acc[mb][2 * p],     ah[mb], bh[p][0], bh[p][1]);
                    mma16816(acc[mb][2 * p + 1], ah[mb], bh[p][2], bh[p][3]);
                    mma16816(acc[mb][2 * p],     ah[mb], bl[p][0], bl[p][1]);
                    mma16816(acc[mb][2 * p + 1], ah[mb], bl[p][2], bl[p][3]);
                    mma16816(acc[mb][2 * p],     al[mb], bh[p][0], bh[p][1]);
                    mma16816(acc[mb][2 * p + 1], al[mb], bh[p][2], bh[p][3]);
                }
        }
        __syncthreads();
    }

    const int crow = lane >> 2;
    const int ccol = (lane & 3) * 2;
#pragma unroll
    for (int mb = 0; mb < 2; mb++) {
#pragma unroll
        for (int nb = 0; nb < 8; nb++) {
            int m = m0 + wm * 32 + mb * 16 + crow;
            int n = n0 + wn * 64 + nb * 8 + ccol;
            *(float2*)&C[(size_t)m * Ntot + n]       = make_float2(acc[mb][nb][0], acc[mb][nb][1]);
            *(float2*)&C[(size_t)(m + 8) * Ntot + n] = make_float2(acc[mb][nb][2], acc[mb][nb][3]);
        }
    }
}

// ---------------------------------------------------------------------------
// RMSNorm + RoPE (+ sqrt(c) prescale); q0/k0 = sqrt(1 + c|v|^2).
// ---------------------------------------------------------------------------
__global__ __launch_bounds__(256) void rms_rope_kernel(
    const float* __restrict__ qkv,
    char* __restrict__ qbh, char* __restrict__ qbl,
    char* __restrict__ kbh, char* __restrict__ kbl,
    float* __restrict__ q0, float* __restrict__ k0,
    float* __restrict__ qn, const float* __restrict__ curv) {
    const int wid = threadIdx.x >> 5;
    const int lane = threadIdx.x & 31;
    const int vi = blockIdx.x * 8 + wid;
    const int t = vi & 2047;
    const int hh = vi >> 11;

    const float* vec;
    size_t obase;
    char *oh, *ol;
    if (hh < NH) {
        vec = qkv + (size_t)t * NQKV + hh * HD;
        obase = ((size_t)t * NH + hh) * HD; oh = qbh; ol = qbl;
    } else {
        vec = qkv + (size_t)t * NQKV + 1024 + (hh - NH) * HD;
        obase = ((size_t)t * NKV + (hh - NH)) * HD; oh = kbh; ol = kbl;
    }
    float x1 = vec[lane], x2 = vec[lane + 32];
    float ss = x1 * x1 + x2 * x2;
#pragma unroll
    for (int o = 16; o >= 1; o >>= 1) ss += __shfl_xor_sync(0xffffffffu, ss, o);

    float inv = rsqrtf(ss * (1.0f / 64.0f) + EPSN);
    x1 *= inv; x2 *= inv;

    float invf = expf(-(float)lane * 0.28782313662425572f);
    float ang = (float)t * invf;
    float sv, cv;
    sincosf(ang, &sv, &cv);
    float c = *curv;
    float sqc = sqrtf(c);
    float o1 = fmaf(x1, cv, x2 * sv) * sqc;
    float o2 = fmaf(-x1, sv, x2 * cv) * sqc;

    float r1, r2;
    uint16_t h1 = bf_hi(o1, r1), h2 = bf_hi(o2, r2);
    ((uint16_t*)oh)[obase + lane]      = h1;
    ((uint16_t*)oh)[obase + lane + 32] = h2;
    ((uint16_t*)ol)[obase + lane]      = bf_of(r1);
    ((uint16_t*)ol)[obase + lane + 32] = bf_of(r2);

    if (lane == 0) {
        float sum2 = ss * inv * inv;
        float h0 = sqrtf(1.0f + c * sum2);
        if (hh < NH) {
            q0[t * NH + hh] = h0;
            qn[t * NH + hh] = sqrtf(sum2);
        } else {
            k0[t * NKV + (hh - NH)] = h0;
        }
    }
}

// ---------------------------------------------------------------------------
// V slice conversion from fused buffer -> fp16 hi/lo
// ---------------------------------------------------------------------------
__global__ __launch_bounds__(256) void v_conv(const float* __restrict__ qkv,
                                              char* __restrict__ vbh,
                                              char* __restrict__ vbl) {
    int i = blockIdx.x * 256 + threadIdx.x;
    if (i >= TT * 64) return;
    int t = i >> 6, j = i & 63;
    float4 v = *(const float4*)&qkv[(size_t)t * NQKV + 1280 + j * 4];
    union { uint16_t u[4]; uint2 v2; } h, l;
    float f[4] = {v.x, v.y, v.z, v.w};
#pragma unroll
    for (int jj = 0; jj < 4; jj++) {
        float rem;
        h.u[jj] = f16_hi(f[jj], rem);
        l.u[jj] = f16_of(rem);
    }
    ((uint2*)vbh)[t * 64 + j] = h.v2;
    ((uint2*)vbl)[t * 64 + j] = l.v2;
}

// ---------------------------------------------------------------------------
// Tensor-core flash hyperbolic attention.
// CTA = 128 q-rows x 1 head, 8 warps (2 CTAs/SM). Split-K via 24-item table.
// S = QK^T bf16 3-term; P fp16 single; PV fp16 2-term (V fp16 hi/lo).
// ---------------------------------------------------------------------------
#define FA_STAGE_B 32768
#define FA_SMEM_BYTES (2 * FA_STAGE_B + 2560)

__global__ void __launch_bounds__(256, 2) flash_attn_mma(
    const char* __restrict__ Qh, const char* __restrict__ Ql,
    const char* __restrict__ Kh, const char* __restrict__ Kl,
    const char* __restrict__ Vh, const char* __restrict__ Vl,
    const float* __restrict__ q0a, const float* __restrict__ k0a,
    const float* __restrict__ temp, const float* __restrict__ curv,
    float* __restrict__ oacc1, float* __restrict__ oacc2,
    float* __restrict__ lacc1, float* __restrict__ lacc2) {
    extern __shared__ __align__(16) char smraw[];
    const uint32_t sb0 = (smem_u32(smraw) + 1023) & ~1023u;
    const uint32_t stg[2] = { sb0, sb0 + FA_STAGE_B };
    float* q0s = (float*)(smraw + (sb0 - smem_u32(smraw)) + 2 * FA_STAGE_B);
    float* k0st0 = q0s + 128;
    float* k0st1 = k0st0 + 64;

    const int tid = threadIdx.x;
    const int lane = tid & 31;
    const int wp = tid >> 5;                  // 0..7
    const int h = blockIdx.x;
    const int cidx = blockIdx.y;

    const int b   = c_ib[cidx];
    const int tl0 = c_it0[cidx];
    const int tl1 = c_it1[cidx];
    const int t0 = b * 128;
    const int kvh = h >> 2;

    float* ob = (tl0 == 0) ? oacc1 : oacc2;
    float* lb = (tl0 == 0) ? lacc1 : lacc2;

    const float sscale = rsqrtf(*curv) / temp[h];
    const float loclamp = 1.0f + 1e-5f;

    // ---- stage Q tile (128 rows, hi/lo) into stage0 ----
    {
        const char* qs[2] = { Qh, Ql };
        for (int idx = tid; idx < 2048; idx += 256) {
            int mtx = idx >> 10, rem = idx & 1023, row = rem >> 3, u = rem & 7;
            const char* src = qs[mtx] + ((size_t)(t0 + row) * NH + h) * 128 + u * 16;
            sts128(stg[0] + mtx * 16384 + SW128((uint32_t)(row * 128 + u * 16)), *(const uint4*)src);
        }
        if (tid < 128) q0s[tid] = q0a[(t0 + tid) * NH + h];
    }
    __syncthreads();

    // ---- Q fragments to registers (warp wp: rows 16wp..16wp+15) ----
    uint32_t qa_h[4][4], qa_l[4][4];
    const int g = lane >> 3, lr = lane & 7;
    {
        const int row = 16 * wp + (g & 1) * 8 + lr;
#pragma unroll
        for (int ks = 0; ks < 4; ks++) {
            uint32_t off = SW128((uint32_t)(row * 128 + ks * 32 + (g >> 1) * 16));
            ldsm_x4(qa_h[ks], stg[0] + off);
            ldsm_x4(qa_l[ks], stg[0] + 16384 + off);
        }
    }
    const int r = lane >> 2;
    const int colb = (lane & 3) * 2;
    const float q0r0 = q0s[16 * wp + r];
    const float q0r1 = q0s[16 * wp + 8 + r];
    const int rl0 = t0 + 16 * wp + r;
    const int rl1 = rl0 + 8;
    __syncthreads();

    float o[8][4];
#pragma unroll
    for (int i = 0; i < 8; i++)
#pragma unroll
        for (int j = 0; j < 4; j++) o[i][j] = 0.f;
    float lsum0 = 0.f, lsum1 = 0.f;

    const char* kvsrc[4] = { Kh + kvh * 128, Kl + kvh * 128, Vh + kvh * 128, Vl + kvh * 128 };

    auto kv_load = [&](int c0, uint32_t sbase, float* k0dst) {
        for (int idx = tid; idx < 2048; idx += 256) {
            int mtx = idx >> 9, rem = idx & 511, row = rem >> 3, u = rem & 7;
            const char* src = kvsrc[mtx] + (size_t)(c0 + row) * 512 + u * 16;
            cpasync16(sbase + mtx * 8192 + SW128((uint32_t)(row * 128 + u * 16)), src);
        }
        if (tid < 64) k0dst[tid] = k0a[(c0 + tid) * NKV + kvh];
    };

    kv_load(tl0 * 64, stg[tl0 & 1], (tl0 & 1) ? k0st1 : k0st0);
    cpasync_commit();

    for (int ch = tl0; ch < tl1; ch++) {
        if (ch + 1 < tl1) {
            kv_load((ch + 1) * 64, stg[(ch + 1) & 1], ((ch + 1) & 1) ? k0st1 : k0st0);
            cpasync_commit();
            cpasync_wait<1>();
        } else {
            cpasync_wait<0>();
        }
        __syncthreads();

        const uint32_t sKh = stg[ch & 1], sKl = sKh + 8192, sVh = sKh + 16384, sVl = sKh + 24576;
        const float* k0s = (ch & 1) ? k0st1 : k0st0;
        const int cbase = ch * 64;

        // ---- S = Q K^T (3-term bf16) ----
        float sc[8][4];
#pragma unroll
        for (int i = 0; i < 8; i++)
#pragma unroll
            for (int j = 0; j < 4; j++) sc[i][j] = 0.f;
        {
#pragma unroll
            for (int ks = 0; ks < 4; ks++) {
                const int dby = ks * 32 + (g >> 1) * 16;
#pragma unroll
                for (int p = 0; p < 4; p++) {
                    const int row = p * 16 + (g & 1) * 8 + lr;
                    uint32_t off = SW128((uint32_t)(row * 128 + dby));
                    uint32_t bh[4], bl[4];
                    ldsm_x4(bh, sKh + off);
                    ldsm_x4(bl, sKl + off);
                    mma16816(sc[2 * p],     qa_h[ks], bh[0], bh[2]);
                    mma16816(sc[2 * p + 1], qa_h[ks], bh[1], bh[3]);
                    mma16816(sc[2 * p],     qa_h[ks], bl[0], bl[2]);
                    mma16816(sc[2 * p + 1], qa_h[ks], bl[1], bl[3]);
                    mma16816(sc[2 * p],     qa_l[ks], bh[0], bh[2]);
                    mma16816(sc[2 * p + 1], qa_l[ks], bh[1], bh[3]);
                }
            }
        }

        // ---- hyperbolic transform -> weights; pack P fp16 single ----
        uint32_t ph[4][4];
#pragma unroll
        for (int nb = 0; nb < 8; nb++) {
            float k00 = k0s[nb * 8 + colb];
            float k01 = k0s[nb * 8 + colb + 1];
            const int cl0 = cbase + nb * 8 + colb, cl1 = cl0 + 1;
            float w0, w1, w2, w3;
            {
                float arg = fmaxf(fmaf(q0r0, k00, -sc[nb][0]), loclamp);
                float z = arg + fsqrt_ap(fmaf(arg, arg, -1.f));
                w0 = fex2(-sscale * flg2(z));
            }
            {
                float arg = fmaxf(fmaf(q0r0, k01, -sc[nb][1]), loclamp);
                float z = arg + fsqrt_ap(fmaf(arg, arg, -1.f));
                w1 = fex2(-sscale * flg2(z));
            }
            {
                float arg = fmaxf(fmaf(q0r1, k00, -sc[nb][2]), loclamp);
                float z = arg + fsqrt_ap(fmaf(arg, arg, -1.f));
                w2 = fex2(-sscale * flg2(z));
            }
            {
                float arg = fmaxf(fmaf(q0r1, k01, -sc[nb][3]), loclamp);
                float z = arg + fsqrt_ap(fmaf(arg, arg, -1.f));
                w3 = fex2(-sscale * flg2(z));
            }
            if (cl0 > rl0) w0 = 0.f;
            if (cl1 > rl0) w1 = 0.f;
            if (cl0 > rl1) w2 = 0.f;
            if (cl1 > rl1) w3 = 0.f;
            lsum0 += w0 + w1;
            lsum1 += w2 + w3;
            uint32_t h01 = (uint32_t)f16_of(w0) | ((uint32_t)f16_of(w1) << 16);
            uint32_t h23 = (uint32_t)f16_of(w2) | ((uint32_t)f16_of(w3) << 16);
            int ks = nb >> 1, ix = (nb & 1) * 2;
            ph[ks][ix] = h01; ph[ks][ix + 1] = h23;
        }

        // ---- O += P V (fp16: P single x V hi/lo = 2-term) ----
        {
#pragma unroll
            for (int ks = 0; ks < 4; ks++) {
                const int rowv = ks * 16 + (g & 1) * 8 + lr;
#pragma unroll
                for (int dp = 0; dp < 4; dp++) {
                    uint32_t off = SW128((uint32_t)(rowv * 128 + dp * 32 + (g >> 1) * 16));
                    uint32_t bvh[4], bvl[4];
                    ldsm_x4_t(bvh, sVh + off);
                    ldsm_x4_t(bvl, sVl + off);
                    mma16816f16(o[2 * dp],     ph[ks], bvh[0], bvh[1]);
                    mma16816f16(o[2 * dp + 1], ph[ks], bvh[2], bvh[3]);
                    mma16816f16(o[2 * dp],     ph[ks], bvl[0], bvl[1]);
                    mma16816f16(o[2 * dp + 1], ph[ks], bvl[2], bvl[3]);
                }
            }
        }
        __syncthreads();
    }

    // ---- epilogue: store unnormalized partials ----
    lsum0 += __shfl_xor_sync(0xffffffffu, lsum0, 1);
    lsum0 += __shfl_xor_sync(0xffffffffu, lsum0, 2);
    lsum1 += __shfl_xor_sync(0xffffffffu, lsum1, 1);
    lsum1 += __shfl_xor_sync(0xffffffffu, lsum1, 2);

#pragma unroll
    for (int nb = 0; nb < 8; nb++) {
        int col = h * 64 + nb * 8 + colb;
        *(float2*)&ob[(size_t)rl0 * DM + col] = make_float2(o[nb][0], o[nb][1]);
        *(float2*)&ob[(size_t)rl1 * DM + col] = make_float2(o[nb][2], o[nb][3]);
    }
    if ((lane & 3) == 0) {
        lb[rl0 * NH + h] = lsum0;
        lb[rl1 * NH + h] = lsum1;
    }
}

// ---------------------------------------------------------------------------
// merge split partials, normalize, emit bf16 hi/lo attn output.
// ---------------------------------------------------------------------------
__global__ __launch_bounds__(256) void merge_norm(
    const float* __restrict__ oacc1, const float* __restrict__ oacc2,
    const float* __restrict__ lacc1, const float* __restrict__ lacc2,
    char* __restrict__ ah, char* __restrict__ al) {
    int j = threadIdx.x;
    int rowid = blockIdx.x * 16 + (j >> 4);
    int t = rowid >> 4;
    int hh = rowid & 15;
    int dd = (j & 15) * 4;
    bool two = (t >= 1024);

    float l = lacc1[rowid] + (two ? lacc2[rowid] : 0.f);
    size_t base = (size_t)t * DM + hh * 64 + dd;
    float4 ov = *(const float4*)&oacc1[base];
    if (two) {
        float4 o2 = *(const float4*)&oacc2[base];
        ov.x += o2.x; ov.y += o2.y; ov.z += o2.z; ov.w += o2.w;
    }
    float invl = 1.0f / l;
    float f[4] = {ov.x * invl, ov.y * invl, ov.z * invl, ov.w * invl};
    union { uint16_t u[4]; uint2 v; } hb, lb2;
#pragma unroll
    for (int k = 0; k < 4; k++) {
        float rem;
        hb.u[k] = bf_hi(f[k], rem);
        lb2.u[k] = bf_of(rem);
    }
    *(uint2*)(ah + base * 2) = hb.v;
    *(uint2*)(al + base * 2) = lb2.v;
}

// ---------------------------------------------------------------------------
// spatial_norm: two-stage reduction
// ---------------------------------------------------------------------------
__global__ __launch_bounds__(256) void norm_partial(const float* __restrict__ qn,
                                                    float* __restrict__ part) {
    __shared__ float red[256];
    int tid = threadIdx.x;
    float s = 0.f;
    for (int i = blockIdx.x * 256 + tid; i < TT * NH; i += 32 * 256) s += qn[i];
    red[tid] = s;
    __syncthreads();
#pragma unroll
    for (int k = 128; k > 0; k >>= 1) {
        if (tid < k) red[tid] += red[tid + k];
        __syncthreads();
    }
    if (tid == 0) part[blockIdx.x] = red[0];
}
__global__ __launch_bounds__(32) void norm_final(const float* __restrict__ part,
                                                 float* __restrict__ out_scalar) {
    int tid = threadIdx.x;
    float s = part[tid];
#pragma unroll
    for (int o = 16; o >= 1; o >>= 1) s += __shfl_xor_sync(0xffffffffu, s, o);
    if (tid == 0) *out_scalar = s * (1.0f / (float)(TT * NH));
}

// ---------------------------------------------------------------------------
// Launch
// ---------------------------------------------------------------------------
extern "C" void kernel_launch(void* const* d_in, const int* in_sizes, int n_in,
                              void* d_out, int out_size) {
    const float* x    = (const float*)d_in[0];
    const float* q_w  = (const float*)d_in[1];
    const float* k_w  = (const float*)d_in[2];
    const float* v_w  = (const float*)d_in[3];
    const float* o_w  = (const float*)d_in[4];
    const float* temp = (const float*)d_in[5];
    const float* curv = (const float*)d_in[6];
    float* out = (float*)d_out;

    float *pqkv, *pq0, *pk0, *pqn, *ppart, *po1, *po2, *pl1, *pl2;
    char *xh, *xl, *wh, *wl, *owh, *owl, *ah, *al;
    char *qbh, *qbl, *kbh, *kbl, *vbh, *vbl;
    cudaGetSymbolAddress((void**)&pqkv, g_qkv);
    cudaGetSymbolAddress((void**)&pq0, g_q0);
    cudaGetSymbolAddress((void**)&pk0, g_k0);
    cudaGetSymbolAddress((void**)&pqn, g_qn);
    cudaGetSymbolAddress((void**)&ppart, g_part);
    cudaGetSymbolAddress((void**)&po1, g_oacc1);
    cudaGetSymbolAddress((void**)&po2, g_oacc2);
    cudaGetSymbolAddress((void**)&pl1, g_lacc1);
    cudaGetSymbolAddress((void**)&pl2, g_lacc2);
    cudaGetSymbolAddress((void**)&xh, g_xh);
    cudaGetSymbolAddress((void**)&xl, g_xl);
    cudaGetSymbolAddress((void**)&wh, g_wh);
    cudaGetSymbolAddress((void**)&wl, g_wl);
    cudaGetSymbolAddress((void**)&owh, g_owh);
    cudaGetSymbolAddress((void**)&owl, g_owl);
    cudaGetSymbolAddress((void**)&ah, g_ah);
    cudaGetSymbolAddress((void**)&al, g_al);
    cudaGetSymbolAddress((void**)&qbh, g_qbh);
    cudaGetSymbolAddress((void**)&qbl, g_qbl);
    cudaGetSymbolAddress((void**)&kbh, g_kbh);
    cudaGetSymbolAddress((void**)&kbl, g_kbl);
    cudaGetSymbolAddress((void**)&vbh, g_vbh);
    cudaGetSymbolAddress((void**)&vbl, g_vbl);

    cudaFuncSetAttribute(gemm_mma_hl, cudaFuncAttributeMaxDynamicSharedMemorySize,
                         GEMM_SMEM_BYTES);
    cudaFuncSetAttribute(flash_attn_mma, cudaFuncAttributeMaxDynamicSharedMemorySize,
                         FA_SMEM_BYTES);

    char* qwh = wh;                         char* qwl = wl;
    char* kwh = wh + (size_t)1024 * DM * 2; char* kwl = wl + (size_t)1024 * DM * 2;
    char* vwh = wh + (size_t)1280 * DM * 2; char* vwl = wl + (size_t)1280 * DM * 2;

    conv_all<<<(N4_TOT / 4 + 255) / 256, 256>>>(x, q_w, k_w, v_w, o_w,
                                                xh, xl, qwh, qwl, kwh, kwl,
                                                vwh, vwl, owh, owl);

    gemm_mma_hl<<<dim3(NQKV / 128, TT / 128), 256, GEMM_SMEM_BYTES>>>(
        xh, xl, wh, wl, pqkv, NQKV, DM);

    rms_rope_kernel<<<TT * (NH + NKV) / 8, 256>>>(pqkv, qbh, qbl, kbh, kbl,
                                                  pq0, pk0, pqn, curv);
    v_conv<<<(TT * 64 + 255) / 256, 256>>>(pqkv, vbh, vbl);

    flash_attn_mma<<<dim3(NH, 24), 256, FA_SMEM_BYTES>>>(
        qbh, qbl, kbh, kbl, vbh, vbl, pq0, pk0, temp, curv,
        po1, po2, pl1, pl2);

    merge_norm<<<TT * NH / 16, 256>>>(po1, po2, pl1, pl2, ah, al);

    gemm_mma_hl<<<dim3(DM / 128, TT / 128), 256, GEMM_SMEM_BYTES>>>(
        ah, al, owh, owl, out, DM, DM);

    norm_partial<<<32, 256>>>(pqn, ppart);
    norm_final<<<1, 32>>>(ppart, out + (out_size - 1));
}